// round 12
// baseline (speedup 1.0000x reference)
#include <cuda_runtime.h>
#include <cstdint>
#include <cstddef>

// FPS with EXACT warp-chunk pruning + register mindist.
// B=8, N=131072, NPOINT=1024. 8 clusters x 8 CTAs x 512 threads.
// One-time Morton(32^3) counting sort -> g_reorder (xyz + orig idx, L2).
// 256 chunks/batch of 512 pts; chunk c -> CTA c%8, warp (c/8)%16, slot (c/8)/16
// (2 chunks per warp; spatial neighbors in different CTAs).
// mindist lives in REGISTERS of the owning warp (persists across skips).
// Per step, per chunk: exact sphere-skip test; if active, 16 LDG.128 +
// inline update/argmax (max dist, min orig idx) + one warp REDUX -> meta.
// meta[] IS the block-reduce input: warp0 reduces 32 metas -> DSMEM slots of
// all 8 peers; one barrier.cluster; every warp reduces 8 slots -> centroid
// in registers. Skips are exact no-ops => output bit-identical to brute force.

#define NB       8
#define NPTS     131072
#define NSAMP    1024
#define CSIZE    8
#define TPB      512
#define PPB      (NPTS / CSIZE)      // 16384 points per CTA
#define NWARPS   (TPB / 32)          // 16
#define NCELLS   32768               // 32^3 Morton cells
#define CHSZ     512                 // points per chunk
#define NCH_C    32                  // chunks per CTA
#define CPW      2                   // chunks per warp
#define QPC      (CHSZ / 32)         // 16 points per thread per chunk

static __device__ float4   g_reorder[NB][NPTS];    // 16 MB scratch (L2-resident)
static __device__ unsigned g_hist[NB][NCELLS];     // re-zeroed every launch

struct __align__(16) Red { unsigned v, i; float x, y, z; unsigned pad[3]; };  // 32B

struct Smem {
    float4   gsph[NCH_C];            // chunk center.xyz, inflated radius
    Red      meta[NCH_C];            // cached {maxdist, argidx, coords}
    Red      slots[2][CSIZE];
    unsigned scanp[TPB];
};

// ---------- asm helpers ----------
__device__ __forceinline__ unsigned ctarank() {
    unsigned r; asm("mov.u32 %0, %%cluster_ctarank;" : "=r"(r)); return r;
}
__device__ __forceinline__ unsigned cvta_s(const void* p) {
    unsigned r;
    asm("{ .reg .u64 t; cvta.to.shared.u64 t, %1; cvt.u32.u64 %0, t; }"
        : "=r"(r) : "l"(p));
    return r;
}
__device__ __forceinline__ unsigned mapa_s(unsigned laddr, unsigned rank) {
    unsigned r;
    asm("mapa.shared::cluster.u32 %0, %1, %2;" : "=r"(r) : "r"(laddr), "r"(rank));
    return r;
}
__device__ __forceinline__ void st_cluster_v4(unsigned raddr, unsigned a, unsigned b,
                                              unsigned c, unsigned d) {
    asm volatile("st.shared::cluster.v4.b32 [%0], {%1,%2,%3,%4};"
                 :: "r"(raddr), "r"(a), "r"(b), "r"(c), "r"(d) : "memory");
}
__device__ __forceinline__ void st_cluster_u32(unsigned raddr, unsigned v) {
    asm volatile("st.shared::cluster.u32 [%0], %1;" :: "r"(raddr), "r"(v) : "memory");
}
__device__ __forceinline__ void cluster_bar() {
    asm volatile("barrier.cluster.arrive.aligned;" ::: "memory");
    asm volatile("barrier.cluster.wait.aligned;"   ::: "memory");
}
__device__ __forceinline__ unsigned p1b2(unsigned x) {
    x &= 0x3ffu;
    x = (x | (x << 16)) & 0x030000FFu;
    x = (x | (x << 8))  & 0x0300F00Fu;
    x = (x | (x << 4))  & 0x030C30C3u;
    x = (x | (x << 2))  & 0x09249249u;
    return x;
}
__device__ __forceinline__ unsigned cell_of(float x, float y, float z) {
    int cx = (int)((x + 5.0f) * 3.2f); cx = cx < 0 ? 0 : (cx > 31 ? 31 : cx);
    int cy = (int)((y + 5.0f) * 3.2f); cy = cy < 0 ? 0 : (cy > 31 ? 31 : cy);
    int cz = (int)((z + 5.0f) * 3.2f); cz = cz < 0 ? 0 : (cz > 31 ? 31 : cz);
    return p1b2((unsigned)cx) | (p1b2((unsigned)cy) << 1) | (p1b2((unsigned)cz) << 2);
}

__global__ void __launch_bounds__(TPB, 1)
fps_kernel(const float* __restrict__ xyz, float* __restrict__ out) {
    __shared__ Smem s;

    const int      tid  = threadIdx.x;
    const unsigned lane = tid & 31;
    const unsigned warp = (unsigned)tid >> 5;
    const unsigned rank = ctarank();
    const int      batch = blockIdx.x / CSIZE;

    const float* __restrict__ base = xyz + (size_t)batch * NPTS * 3;
    unsigned* __restrict__ hb = g_hist[batch];
    float4*   __restrict__ rb = g_reorder[batch];

    // ================= one-time spatial binning (R9-R11, verified) =========
    for (int i = (int)rank * (NCELLS / CSIZE) + tid;
         i < (int)(rank + 1) * (NCELLS / CSIZE); i += TPB)
        hb[i] = 0u;
    cluster_bar();

    for (int ii = tid; ii < PPB; ii += TPB) {
        unsigned gi = rank * PPB + (unsigned)ii;
        const float* p = base + (size_t)gi * 3;
        float x = __ldg(p), y = __ldg(p + 1), z = __ldg(p + 2);
        atomicAdd(&hb[cell_of(x, y, z)], 1u);
    }
    cluster_bar();

    if (rank == 0) {
        const int per = NCELLS / TPB;        // 64
        unsigned ssum = 0;
        for (int j = 0; j < per; ++j) ssum += hb[tid * per + j];
        s.scanp[tid] = ssum;
        __syncthreads();
        if (tid == 0) {
            unsigned run = 0;
            for (int i = 0; i < TPB; ++i) { unsigned v = s.scanp[i]; s.scanp[i] = run; run += v; }
        }
        __syncthreads();
        unsigned run = s.scanp[tid];
        for (int j = 0; j < per; ++j) {
            unsigned v = hb[tid * per + j];
            hb[tid * per + j] = run;
            run += v;
        }
    }
    cluster_bar();

    for (int ii = tid; ii < PPB; ii += TPB) {
        unsigned gi = rank * PPB + (unsigned)ii;
        const float* p = base + (size_t)gi * 3;
        float x = __ldg(p), y = __ldg(p + 1), z = __ldg(p + 2);
        unsigned slot = atomicAdd(&hb[cell_of(x, y, z)], 1u);
        rb[slot] = make_float4(x, y, z, __uint_as_float(gi));
    }
    cluster_bar();

    // ---- per-chunk bounding spheres (init-only; two L2 passes is fine) ----
#pragma unroll
    for (int sl = 0; sl < CPW; ++sl) {
        int l = sl * NWARPS + (int)warp;          // local chunk 0..31
        int c = l * CSIZE + (int)rank;            // batch chunk 0..255
        const float4* cb = rb + (size_t)c * CHSZ;
        float sx = 0.f, sy = 0.f, sz = 0.f;
        for (int q = 0; q < QPC; ++q) {
            float4 p = __ldg(cb + q * 32 + lane);
            sx += p.x; sy += p.y; sz += p.z;
        }
#pragma unroll
        for (int off = 16; off > 0; off >>= 1) {
            sx += __shfl_xor_sync(0xffffffffu, sx, off);
            sy += __shfl_xor_sync(0xffffffffu, sy, off);
            sz += __shfl_xor_sync(0xffffffffu, sz, off);
        }
        float gx = sx * (1.0f / CHSZ), gy = sy * (1.0f / CHSZ), gz = sz * (1.0f / CHSZ);
        float d2m = 0.f;
        for (int q = 0; q < QPC; ++q) {
            float4 p = __ldg(cb + q * 32 + lane);
            float dx = p.x - gx, dy = p.y - gy, dz = p.z - gz;
            d2m = fmaxf(d2m, dx * dx + dy * dy + dz * dz);
        }
        unsigned md = __reduce_max_sync(0xffffffffu, __float_as_uint(d2m));
        if (lane == 0) {
            float rad = sqrtf(__uint_as_float(md)) * 1.001f + 1e-6f;
            s.gsph[l] = make_float4(gx, gy, gz, rad);
            s.meta[l].v = 0x7f800000u;   // +inf: never skipped at step 1
            s.meta[l].i = 0u;
        }
    }

    // per-point mindist in REGISTERS (owner-warp private, persists over skips)
    float M[CPW][QPC];
#pragma unroll
    for (int sl = 0; sl < CPW; ++sl)
#pragma unroll
        for (int q = 0; q < QPC; ++q) M[sl][q] = __int_as_float(0x7f800000);

    unsigned rs0 = 0, rs1 = 0;
    if (warp == 0 && lane < CSIZE) {
        rs0 = mapa_s(cvta_s(&s.slots[0][rank]), lane);
        rs1 = mapa_s(cvta_s(&s.slots[1][rank]), lane);
    }

    float cx = __ldg(base + 0);
    float cy = __ldg(base + 1);
    float cz = __ldg(base + 2);
    if (rank == 0 && tid == 0) {
        float* o = out + (size_t)batch * NSAMP * 3;
        o[0] = cx; o[1] = cy; o[2] = cz;
    }
    __syncthreads();
    cluster_bar();   // spheres/metas ready cluster-wide before step 1

    // ================= steady-state FPS loop =================
    for (int t = 1; t < NSAMP; ++t) {
#pragma unroll
        for (int sl = 0; sl < CPW; ++sl) {
            const int l = sl * NWARPS + (int)warp;
            // ---- exact skip test (same bound as R9-R11, verified 3x) ----
            float4 gs = s.gsph[l];
            float gmax = __uint_as_float(s.meta[l].v);
            float ddx = gs.x - cx, ddy = gs.y - cy, ddz = gs.z - cz;
            float dc2 = ddx * ddx + ddy * ddy + ddz * ddz;
            float tt = sqrtf(dc2) - gs.w;
            if ((tt > 0.0f) && (0.998f * tt * tt > gmax)) continue;  // exact no-op

            // ---- active: update 512 pts, inline exact argmax ----
            const int c = l * CSIZE + (int)rank;
            const float4* cb = rb + (size_t)c * CHSZ;
            float bv = -1.0f, bx = 0.f, by = 0.f, bz = 0.f;
            unsigned bi = 0xffffffffu;
#pragma unroll
            for (int q = 0; q < QPC; ++q) {
                float4 p = __ldg(cb + q * 32 + lane);
                float dx = p.x - cx, dy = p.y - cy, dz = p.z - cz;
                float d = dx * dx; d = fmaf(dy, dy, d); d = fmaf(dz, dz, d);
                float mm = fminf(M[sl][q], d);
                M[sl][q] = mm;
                unsigned oi = __float_as_uint(p.w);
                bool take = (mm > bv) || (mm == bv && oi < bi);
                if (take) { bv = mm; bi = oi; bx = p.x; by = p.y; bz = p.z; }
            }
            unsigned vb = __float_as_uint(bv);                 // d >= 0
            unsigned wv = __reduce_max_sync(0xffffffffu, vb);
            unsigned cd = (vb == wv) ? bi : 0xffffffffu;
            unsigned wi = __reduce_min_sync(0xffffffffu, cd);
            if (vb == wv && bi == wi) {                        // unique orig idx
                *reinterpret_cast<uint4*>(&s.meta[l]) =
                    make_uint4(wv, wi, __float_as_uint(bx), __float_as_uint(by));
                s.meta[l].z = bz;
            }
        }
        __syncthreads();   // metas visible block-wide

        const int par = t & 1;

        // ---- warp0: reduce the 32 chunk metas, push to all 8 peers ----
        if (warp == 0) {
            uint4 w4 = *reinterpret_cast<const uint4*>(&s.meta[lane]);  // 32 lanes, 32 metas
            unsigned v = w4.x, i = w4.y, xw = w4.z, yw = w4.w;
            unsigned zw = __float_as_uint(s.meta[lane].z);
            unsigned bv = __reduce_max_sync(0xffffffffu, v);
            unsigned bc = (v == bv) ? i : 0xffffffffu;
            unsigned bi = __reduce_min_sync(0xffffffffu, bc);
            unsigned msk = __ballot_sync(0xffffffffu, bc == bi);
            int L = __ffs(msk) - 1;
            xw = __shfl_sync(0xffffffffu, xw, L);
            yw = __shfl_sync(0xffffffffu, yw, L);
            zw = __shfl_sync(0xffffffffu, zw, L);
            if (lane < CSIZE) {
                unsigned ra = par ? rs1 : rs0;
                st_cluster_v4(ra, bv, bi, xw, yw);
                st_cluster_u32(ra + 16, zw);
            }
        }

        cluster_bar();   // one cluster barrier per step

        // ---- EVERY warp reduces the 8 slots -> next centroid in registers ----
        {
            unsigned v = 0, i = 0xffffffffu, xw = 0, yw = 0, zw = 0;
            if (lane < CSIZE) {
                uint4 w4 = *reinterpret_cast<const uint4*>(&s.slots[par][lane]);
                v = w4.x; i = w4.y; xw = w4.z; yw = w4.w;
                zw = __float_as_uint(s.slots[par][lane].z);
            }
            unsigned cv = __reduce_max_sync(0xffffffffu, v);
            unsigned cc = (v == cv) ? i : 0xffffffffu;
            unsigned ci = __reduce_min_sync(0xffffffffu, cc);
            unsigned msk = __ballot_sync(0xffffffffu, cc == ci);
            int W = __ffs(msk) - 1;
            cx = __uint_as_float(__shfl_sync(0xffffffffu, xw, W));
            cy = __uint_as_float(__shfl_sync(0xffffffffu, yw, W));
            cz = __uint_as_float(__shfl_sync(0xffffffffu, zw, W));
            if (rank == 0 && tid == 0) {
                float* o = out + ((size_t)batch * NSAMP + (size_t)t) * 3;
                o[0] = cx; o[1] = cy; o[2] = cz;
            }
        }
        // hazards: meta[l] is written only by its owner warp, read by warp0
        // after __syncthreads; M[][] is warp-private registers; slots are
        // parity double-buffered across the cluster barrier (proven R3-R11).
    }

    cluster_bar();  // keep CTAs alive until all DSMEM traffic has landed
}

extern "C" void kernel_launch(void* const* d_in, const int* in_sizes, int n_in,
                              void* d_out, int out_size) {
    (void)in_sizes; (void)n_in; (void)out_size;
    const float* xyz = (const float*)d_in[0];
    float* out = (float*)d_out;

    cudaLaunchConfig_t cfg = {};
    cfg.gridDim  = dim3(NB * CSIZE, 1, 1);   // 64 CTAs
    cfg.blockDim = dim3(TPB, 1, 1);
    cfg.dynamicSmemBytes = 0;
    cfg.stream = 0;

    cudaLaunchAttribute attr[1];
    attr[0].id = cudaLaunchAttributeClusterDimension;
    attr[0].val.clusterDim.x = CSIZE;
    attr[0].val.clusterDim.y = 1;
    attr[0].val.clusterDim.z = 1;
    cfg.attrs = attr;
    cfg.numAttrs = 1;

    cudaLaunchKernelEx(&cfg, fps_kernel, xyz, out);
}

// round 13
// speedup vs baseline: 2.9439x; 2.9439x over previous
#include <cuda_runtime.h>
#include <cstdint>
#include <cstddef>

// FPS: B=8, N=131072, NPOINT=1024 -> out [8,1024,3] fp32.
// R3 (best, 1530us) with ONE change: the per-step barrier.cluster is replaced
// by a cluster-8 DSMEM mbarrier exchange (store partial to each peer's slot +
// remote mbarrier.arrive.release; local try_wait.parity.acquire; parity
// double-buffered). Everything else is byte-identical to R3:
// 8 clusters x 8 CTAs x 512 threads; 16 pairs/thread (8 in registers, 8
// streamed pair-major from SMEM); packed-f32x2 update; REDUX argmax
// (max dist, min index); winner coords ride the reduction; every warp
// reduces the 8 slots so the next centroid lands in registers.

#define NB       8
#define NPTS     131072
#define NSAMP    1024
#define CSIZE    8
#define TPB      512
#define PPB      (NPTS / CSIZE)    // 16384 points per CTA
#define PAIRS    (PPB / 2)         // 8192 pairs per CTA
#define REGJ     8                 // pairs/thread in registers
#define TOTJ     16                // pairs/thread total
#define NPT      32                // points/thread
#define NWARPS   (TPB / 32)        // 16

struct __align__(16) Red { unsigned v, i; float x, y, z; unsigned pad[3]; };  // 32B

struct Smem {
    unsigned long long mbar[2];      // double-buffered arrival barriers (count=8)
    Red warpred[NWARPS];
    Red slots[2][CSIZE];
    unsigned long long xs2[PAIRS];   // packed {x_even, x_odd} per pair
    unsigned long long ys2[PAIRS];
    unsigned long long zs2[PAIRS];
};

// ---------- asm helpers ----------
__device__ __forceinline__ unsigned ctarank() {
    unsigned r; asm("mov.u32 %0, %%cluster_ctarank;" : "=r"(r)); return r;
}
__device__ __forceinline__ unsigned cvta_s(const void* p) {
    unsigned r;
    asm("{ .reg .u64 t; cvta.to.shared.u64 t, %1; cvt.u32.u64 %0, t; }"
        : "=r"(r) : "l"(p));
    return r;
}
__device__ __forceinline__ unsigned mapa_s(unsigned laddr, unsigned rank) {
    unsigned r;
    asm("mapa.shared::cluster.u32 %0, %1, %2;" : "=r"(r) : "r"(laddr), "r"(rank));
    return r;
}
__device__ __forceinline__ unsigned long long packf2(float lo, float hi) {
    unsigned long long r;
    asm("mov.b64 %0, {%1, %2};" : "=l"(r) : "f"(lo), "f"(hi));
    return r;
}
__device__ __forceinline__ void unpackf2(unsigned long long v, float& lo, float& hi) {
    asm("mov.b64 {%0, %1}, %2;" : "=f"(lo), "=f"(hi) : "l"(v));
}
__device__ __forceinline__ unsigned long long addx2(unsigned long long a,
                                                    unsigned long long b) {
    unsigned long long r;
    asm("add.rn.f32x2 %0, %1, %2;" : "=l"(r) : "l"(a), "l"(b));
    return r;
}
__device__ __forceinline__ unsigned long long mulx2(unsigned long long a,
                                                    unsigned long long b) {
    unsigned long long r;
    asm("mul.rn.f32x2 %0, %1, %2;" : "=l"(r) : "l"(a), "l"(b));
    return r;
}
__device__ __forceinline__ unsigned long long fmx2(unsigned long long a,
                                                   unsigned long long b,
                                                   unsigned long long c) {
    unsigned long long r;
    asm("fma.rn.f32x2 %0, %1, %2, %3;" : "=l"(r) : "l"(a), "l"(b), "l"(c));
    return r;
}
__device__ __forceinline__ void st_cluster_v4(unsigned raddr, unsigned a, unsigned b,
                                              unsigned c, unsigned d) {
    asm volatile("st.shared::cluster.v4.b32 [%0], {%1,%2,%3,%4};"
                 :: "r"(raddr), "r"(a), "r"(b), "r"(c), "r"(d) : "memory");
}
__device__ __forceinline__ void st_cluster_u32(unsigned raddr, unsigned v) {
    asm volatile("st.shared::cluster.u32 [%0], %1;" :: "r"(raddr), "r"(v) : "memory");
}
__device__ __forceinline__ void mbar_init(unsigned addr, unsigned cnt) {
    asm volatile("mbarrier.init.shared.b64 [%0], %1;" :: "r"(addr), "r"(cnt) : "memory");
}
__device__ __forceinline__ void mbar_arrive_rel_cluster(unsigned raddr) {
    asm volatile("mbarrier.arrive.release.cluster.shared::cluster.b64 _, [%0];"
                 :: "r"(raddr) : "memory");
}
__device__ __forceinline__ void mbar_wait_acq_cluster(unsigned addr, unsigned ph) {
    asm volatile(
        "{\n\t"
        ".reg .pred P;\n\t"
        "WL%=:\n\t"
        "mbarrier.try_wait.parity.acquire.cluster.shared::cta.b64 P, [%0], %1, 0x989680;\n\t"
        "@P bra WD%=;\n\t"
        "bra WL%=;\n\t"
        "WD%=:\n\t"
        "}"
        :: "r"(addr), "r"(ph) : "memory");
}
__device__ __forceinline__ void cluster_bar() {
    asm volatile("barrier.cluster.arrive.aligned;" ::: "memory");
    asm volatile("barrier.cluster.wait.aligned;"   ::: "memory");
}

__global__ void __launch_bounds__(TPB, 1)
fps_kernel(const float* __restrict__ xyz, float* __restrict__ out) {
    extern __shared__ __align__(16) unsigned char smem_raw[];
    Smem* s = reinterpret_cast<Smem*>(smem_raw);

    const int      tid  = threadIdx.x;
    const unsigned lane = tid & 31;
    const unsigned warp = (unsigned)tid >> 5;
    const unsigned rank = ctarank();
    const int      batch = blockIdx.x / CSIZE;

    const float* __restrict__ base = xyz + (size_t)batch * NPTS * 3;
    const unsigned pbase = rank * PPB;

    if (tid == 0) {
        mbar_init(cvta_s(&s->mbar[0]), CSIZE);
        mbar_init(cvta_s(&s->mbar[1]), CSIZE);
    }

    // ---- fill SMEM with ALL pairs (packed), plus register half ----
    for (unsigned P = (unsigned)tid; P < PAIRS; P += TPB) {
        const float2* p = reinterpret_cast<const float2*>(
            base + (size_t)(pbase + 2u * P) * 3);
        float2 a = p[0];  // x0 y0
        float2 b = p[1];  // z0 x1
        float2 c = p[2];  // y1 z1
        s->xs2[P] = packf2(a.x, b.y);
        s->ys2[P] = packf2(a.y, c.x);
        s->zs2[P] = packf2(b.x, c.y);
    }

    unsigned long long X[REGJ], Y[REGJ], Z[REGJ];
#pragma unroll
    for (int j = 0; j < REGJ; ++j) {
        unsigned P = (unsigned)j * TPB + (unsigned)tid;
        const float2* p = reinterpret_cast<const float2*>(
            base + (size_t)(pbase + 2u * P) * 3);
        float2 a = p[0]; float2 b = p[1]; float2 c = p[2];
        X[j] = packf2(a.x, b.y);
        Y[j] = packf2(a.y, c.x);
        Z[j] = packf2(b.x, c.y);
    }

    float m[NPT];
#pragma unroll
    for (int k = 0; k < NPT; ++k) m[k] = __int_as_float(0x7f800000);  // +inf

    // remote slot + mbar addresses for pushes (warp0 lanes < CSIZE)
    unsigned rs0 = 0, rs1 = 0, rb0 = 0, rb1 = 0;
    if (warp == 0 && lane < CSIZE) {
        rs0 = mapa_s(cvta_s(&s->slots[0][rank]), lane);
        rs1 = mapa_s(cvta_s(&s->slots[1][rank]), lane);
        rb0 = mapa_s(cvta_s(&s->mbar[0]), lane);
        rb1 = mapa_s(cvta_s(&s->mbar[1]), lane);
    }
    const unsigned lb0 = cvta_s(&s->mbar[0]);
    const unsigned lb1 = cvta_s(&s->mbar[1]);

    // initial centroid = point 0 of this batch (broadcast L2 load, once)
    float cx = __ldg(base + 0);
    float cy = __ldg(base + 1);
    float cz = __ldg(base + 2);
    if (rank == 0 && tid == 0) {
        float* o = out + (size_t)batch * NSAMP * 3;
        o[0] = cx; o[1] = cy; o[2] = cz;
    }
    __syncthreads();   // smem points ready
    cluster_bar();     // mbarrier init visible cluster-wide before any arrive

    unsigned ph0 = 0, ph1 = 0;

    for (int t = 1; t < NSAMP; ++t) {
        const unsigned long long ncx = packf2(-cx, -cx);
        const unsigned long long ncy = packf2(-cy, -cy);
        const unsigned long long ncz = packf2(-cz, -cz);

        // ---- update mindist; track only the max value ----
        float bm = -1.0f;
#pragma unroll
        for (int j = 0; j < REGJ; ++j) {
            unsigned long long dx = addx2(X[j], ncx);
            unsigned long long dy = addx2(Y[j], ncy);
            unsigned long long dz = addx2(Z[j], ncz);
            unsigned long long dd = mulx2(dx, dx);
            dd = fmx2(dy, dy, dd);
            dd = fmx2(dz, dz, dd);
            float d0, d1; unpackf2(dd, d0, d1);
            float m0 = fminf(m[2 * j], d0);
            float m1 = fminf(m[2 * j + 1], d1);
            m[2 * j] = m0; m[2 * j + 1] = m1;
            bm = fmaxf(bm, fmaxf(m0, m1));
        }
#pragma unroll
        for (int j = REGJ; j < TOTJ; ++j) {
            unsigned P = (unsigned)j * TPB + (unsigned)tid;
            unsigned long long dx = addx2(s->xs2[P], ncx);
            unsigned long long dy = addx2(s->ys2[P], ncy);
            unsigned long long dz = addx2(s->zs2[P], ncz);
            unsigned long long dd = mulx2(dx, dx);
            dd = fmx2(dy, dy, dd);
            dd = fmx2(dz, dz, dd);
            float d0, d1; unpackf2(dd, d0, d1);
            float m0 = fminf(m[2 * j], d0);
            float m1 = fminf(m[2 * j + 1], d1);
            m[2 * j] = m0; m[2 * j + 1] = m1;
            bm = fmaxf(bm, fmaxf(m0, m1));
        }

        // ---- resolve smallest k with m[k]==bm (downward scan) ----
        int kk = 0;
#pragma unroll
        for (int k = NPT - 1; k >= 0; --k)
            if (m[k] == bm) kk = k;

        unsigned Pw   = (unsigned)(kk >> 1) * TPB + (unsigned)tid;
        unsigned gidx = pbase + 2u * Pw + (unsigned)(kk & 1);
        float a0, a1, b0, b1, c0, c1;
        unpackf2(s->xs2[Pw], a0, a1);
        unpackf2(s->ys2[Pw], b0, b1);
        unpackf2(s->zs2[Pw], c0, c1);
        float candx = (kk & 1) ? a1 : a0;
        float candy = (kk & 1) ? b1 : b0;
        float candz = (kk & 1) ? c1 : c0;

        // ---- warp reduce: max dist bits, then min index among maxima ----
        unsigned vb = __float_as_uint(bm);            // d>=0: int order == float order
        unsigned wv = __reduce_max_sync(0xffffffffu, vb);
        unsigned cd = (vb == wv) ? gidx : 0xffffffffu;
        unsigned wi = __reduce_min_sync(0xffffffffu, cd);
        if (cd == wi) {                               // unique winner lane stores
            *reinterpret_cast<uint4*>(&s->warpred[warp]) =
                make_uint4(wv, wi, __float_as_uint(candx), __float_as_uint(candy));
            s->warpred[warp].z = candz;
        }
        __syncthreads();

        const int par = t & 1;

        // ---- block reduce over 16 warp partials + push to all 8 peers ----
        if (warp == 0) {
            unsigned v = 0, i = 0xffffffffu, xb = 0, yb = 0, zb = 0;
            if (lane < NWARPS) {
                uint4 w = *reinterpret_cast<const uint4*>(&s->warpred[lane]);
                v = w.x; i = w.y; xb = w.z; yb = w.w;
                zb = __float_as_uint(s->warpred[lane].z);
            }
            unsigned bv = __reduce_max_sync(0xffffffffu, v);
            unsigned bc = (v == bv) ? i : 0xffffffffu;
            unsigned bi = __reduce_min_sync(0xffffffffu, bc);
            unsigned msk = __ballot_sync(0xffffffffu, bc == bi);
            int L = __ffs(msk) - 1;
            xb = __shfl_sync(0xffffffffu, xb, L);
            yb = __shfl_sync(0xffffffffu, yb, L);
            zb = __shfl_sync(0xffffffffu, zb, L);
            if (lane < CSIZE) {
                unsigned ra = par ? rs1 : rs0;
                st_cluster_v4(ra, bv, bi, xb, yb);
                st_cluster_u32(ra + 16, zb);
                // release-arrive orders the two stores above at the peer
                mbar_arrive_rel_cluster(par ? rb1 : rb0);
            }
        }

        // ---- all warps wait for the 8 arrives on the local barrier ----
        mbar_wait_acq_cluster(par ? lb1 : lb0, par ? ph1 : ph0);
        if (par) ph1 ^= 1; else ph0 ^= 1;

        // ---- EVERY warp reduces the 8 slots -> next centroid in registers ----
        {
            unsigned v = 0, i = 0xffffffffu, xb = 0, yb = 0, zb = 0;
            if (lane < CSIZE) {
                uint4 w = *reinterpret_cast<const uint4*>(&s->slots[par][lane]);
                v = w.x; i = w.y; xb = w.z; yb = w.w;
                zb = __float_as_uint(s->slots[par][lane].z);
            }
            unsigned cv = __reduce_max_sync(0xffffffffu, v);
            unsigned cc = (v == cv) ? i : 0xffffffffu;
            unsigned ci = __reduce_min_sync(0xffffffffu, cc);
            unsigned msk = __ballot_sync(0xffffffffu, cc == ci);
            int W = __ffs(msk) - 1;
            cx = __uint_as_float(__shfl_sync(0xffffffffu, xb, W));
            cy = __uint_as_float(__shfl_sync(0xffffffffu, yb, W));
            cz = __uint_as_float(__shfl_sync(0xffffffffu, zb, W));
            if (rank == 0 && tid == 0) {
                float* o = out + ((size_t)batch * NSAMP + (size_t)t) * 3;
                o[0] = cx; o[1] = cy; o[2] = cz;
            }
        }
        // slots overwrite hazard: a peer can only push step t+2 into my
        // slots[par] after passing its step-t+1 wait, which requires MY t+1
        // arrive, which happens after all my warps finished reading step t's
        // slots (next-iteration __syncthreads precedes my push). Same 2-deep
        // parity pipeline argument as R2/R5 (both passed rel_err 0).
    }

    cluster_bar();  // keep CTAs alive until all in-flight DSMEM has landed
}

extern "C" void kernel_launch(void* const* d_in, const int* in_sizes, int n_in,
                              void* d_out, int out_size) {
    (void)in_sizes; (void)n_in; (void)out_size;
    const float* xyz = (const float*)d_in[0];
    float* out = (float*)d_out;

    cudaFuncSetAttribute(fps_kernel,
                         cudaFuncAttributeMaxDynamicSharedMemorySize,
                         (int)sizeof(Smem));

    cudaLaunchConfig_t cfg = {};
    cfg.gridDim  = dim3(NB * CSIZE, 1, 1);   // 64 CTAs
    cfg.blockDim = dim3(TPB, 1, 1);
    cfg.dynamicSmemBytes = sizeof(Smem);
    cfg.stream = 0;

    cudaLaunchAttribute attr[1];
    attr[0].id = cudaLaunchAttributeClusterDimension;
    attr[0].val.clusterDim.x = CSIZE;
    attr[0].val.clusterDim.y = 1;
    attr[0].val.clusterDim.z = 1;
    cfg.attrs = attr;
    cfg.numAttrs = 1;

    cudaLaunchKernelEx(&cfg, fps_kernel, xyz, out);
}

// round 14
// speedup vs baseline: 3.2820x; 1.1149x over previous
#include <cuda_runtime.h>
#include <cstdint>
#include <cstddef>

// FPS: B=8, N=131072, NPOINT=1024 -> out [8,1024,3] fp32.
// R3 (champion, 1530us) with ONE surgical change: the three packed
// subtractions per pair (add.rn.f32x2, which decays to 2x scalar FADD)
// are replaced by fma.rn.f32x2(p, {1,1}, -c)  -- a single FFMA2, bit-exact.
// Everything else is byte-identical to R3: 8 clusters x 8 CTAs x 512 thr;
// 16 pairs/thread (8 in registers, 8 streamed pair-major from SMEM);
// REDUX argmax (max dist, min index); winner coords ride the reduction ->
// DSMEM slots; ONE barrier.cluster per step; every warp reduces the 8
// slots so the next centroid lands in registers.

#define NB       8
#define NPTS     131072
#define NSAMP    1024
#define CSIZE    8
#define TPB      512
#define PPB      (NPTS / CSIZE)    // 16384 points per CTA
#define PAIRS    (PPB / 2)         // 8192 pairs per CTA
#define REGJ     8                 // pairs/thread in registers
#define TOTJ     16                // pairs/thread total
#define NPT      32                // points/thread
#define NWARPS   (TPB / 32)        // 16

struct __align__(16) Red { unsigned v, i; float x, y, z; unsigned pad[3]; };  // 32B

struct Smem {
    Red warpred[NWARPS];
    Red slots[2][CSIZE];
    unsigned long long xs2[PAIRS];   // packed {x_even, x_odd} per pair
    unsigned long long ys2[PAIRS];
    unsigned long long zs2[PAIRS];
};

// ---------- asm helpers ----------
__device__ __forceinline__ unsigned ctarank() {
    unsigned r; asm("mov.u32 %0, %%cluster_ctarank;" : "=r"(r)); return r;
}
__device__ __forceinline__ unsigned cvta_s(const void* p) {
    unsigned r;
    asm("{ .reg .u64 t; cvta.to.shared.u64 t, %1; cvt.u32.u64 %0, t; }"
        : "=r"(r) : "l"(p));
    return r;
}
__device__ __forceinline__ unsigned mapa_s(unsigned laddr, unsigned rank) {
    unsigned r;
    asm("mapa.shared::cluster.u32 %0, %1, %2;" : "=r"(r) : "r"(laddr), "r"(rank));
    return r;
}
__device__ __forceinline__ unsigned long long packf2(float lo, float hi) {
    unsigned long long r;
    asm("mov.b64 %0, {%1, %2};" : "=l"(r) : "f"(lo), "f"(hi));
    return r;
}
__device__ __forceinline__ void unpackf2(unsigned long long v, float& lo, float& hi) {
    asm("mov.b64 {%0, %1}, %2;" : "=f"(lo), "=f"(hi) : "l"(v));
}
__device__ __forceinline__ unsigned long long mulx2(unsigned long long a,
                                                    unsigned long long b) {
    unsigned long long r;
    asm("mul.rn.f32x2 %0, %1, %2;" : "=l"(r) : "l"(a), "l"(b));
    return r;
}
__device__ __forceinline__ unsigned long long fmx2(unsigned long long a,
                                                   unsigned long long b,
                                                   unsigned long long c) {
    unsigned long long r;
    asm("fma.rn.f32x2 %0, %1, %2, %3;" : "=l"(r) : "l"(a), "l"(b), "l"(c));
    return r;
}
__device__ __forceinline__ void st_cluster_v4(unsigned raddr, unsigned a, unsigned b,
                                              unsigned c, unsigned d) {
    asm volatile("st.shared::cluster.v4.b32 [%0], {%1,%2,%3,%4};"
                 :: "r"(raddr), "r"(a), "r"(b), "r"(c), "r"(d) : "memory");
}
__device__ __forceinline__ void st_cluster_u32(unsigned raddr, unsigned v) {
    asm volatile("st.shared::cluster.u32 [%0], %1;" :: "r"(raddr), "r"(v) : "memory");
}
__device__ __forceinline__ void cluster_bar() {
    asm volatile("barrier.cluster.arrive.aligned;" ::: "memory");
    asm volatile("barrier.cluster.wait.aligned;"   ::: "memory");
}

__global__ void __launch_bounds__(TPB, 1)
fps_kernel(const float* __restrict__ xyz, float* __restrict__ out) {
    extern __shared__ __align__(16) unsigned char smem_raw[];
    Smem* s = reinterpret_cast<Smem*>(smem_raw);

    const int      tid  = threadIdx.x;
    const unsigned lane = tid & 31;
    const unsigned warp = (unsigned)tid >> 5;
    const unsigned rank = ctarank();
    const int      batch = blockIdx.x / CSIZE;

    const float* __restrict__ base = xyz + (size_t)batch * NPTS * 3;
    const unsigned pbase = rank * PPB;

    // ---- fill SMEM with ALL pairs (packed), plus register half ----
    for (unsigned P = (unsigned)tid; P < PAIRS; P += TPB) {
        const float2* p = reinterpret_cast<const float2*>(
            base + (size_t)(pbase + 2u * P) * 3);
        float2 a = p[0];  // x0 y0
        float2 b = p[1];  // z0 x1
        float2 c = p[2];  // y1 z1
        s->xs2[P] = packf2(a.x, b.y);
        s->ys2[P] = packf2(a.y, c.x);
        s->zs2[P] = packf2(b.x, c.y);
    }

    unsigned long long X[REGJ], Y[REGJ], Z[REGJ];
#pragma unroll
    for (int j = 0; j < REGJ; ++j) {
        unsigned P = (unsigned)j * TPB + (unsigned)tid;
        const float2* p = reinterpret_cast<const float2*>(
            base + (size_t)(pbase + 2u * P) * 3);
        float2 a = p[0]; float2 b = p[1]; float2 c = p[2];
        X[j] = packf2(a.x, b.y);
        Y[j] = packf2(a.y, c.x);
        Z[j] = packf2(b.x, c.y);
    }

    float m[NPT];
#pragma unroll
    for (int k = 0; k < NPT; ++k) m[k] = __int_as_float(0x7f800000);  // +inf

    // remote slot addresses for pushes (warp0 lanes < CSIZE), both parities
    unsigned rs0 = 0, rs1 = 0;
    if (warp == 0 && lane < CSIZE) {
        rs0 = mapa_s(cvta_s(&s->slots[0][rank]), lane);
        rs1 = mapa_s(cvta_s(&s->slots[1][rank]), lane);
    }

    // initial centroid = point 0 of this batch (broadcast L2 load, once)
    float cx = __ldg(base + 0);
    float cy = __ldg(base + 1);
    float cz = __ldg(base + 2);
    if (rank == 0 && tid == 0) {
        float* o = out + (size_t)batch * NSAMP * 3;
        o[0] = cx; o[1] = cy; o[2] = cz;
    }
    __syncthreads();   // smem points ready

    const unsigned long long ONE2 = packf2(1.0f, 1.0f);

    for (int t = 1; t < NSAMP; ++t) {
        const unsigned long long ncx = packf2(-cx, -cx);
        const unsigned long long ncy = packf2(-cy, -cy);
        const unsigned long long ncz = packf2(-cz, -cz);

        // ---- update mindist; track only the max value ----
        // p - c computed as fma(p, 1, -c): single FFMA2, rounding identical.
        float bm = -1.0f;
#pragma unroll
        for (int j = 0; j < REGJ; ++j) {
            unsigned long long dx = fmx2(X[j], ONE2, ncx);
            unsigned long long dy = fmx2(Y[j], ONE2, ncy);
            unsigned long long dz = fmx2(Z[j], ONE2, ncz);
            unsigned long long dd = mulx2(dx, dx);
            dd = fmx2(dy, dy, dd);
            dd = fmx2(dz, dz, dd);
            float d0, d1; unpackf2(dd, d0, d1);
            float m0 = fminf(m[2 * j], d0);
            float m1 = fminf(m[2 * j + 1], d1);
            m[2 * j] = m0; m[2 * j + 1] = m1;
            bm = fmaxf(bm, fmaxf(m0, m1));
        }
#pragma unroll
        for (int j = REGJ; j < TOTJ; ++j) {
            unsigned P = (unsigned)j * TPB + (unsigned)tid;
            unsigned long long dx = fmx2(s->xs2[P], ONE2, ncx);
            unsigned long long dy = fmx2(s->ys2[P], ONE2, ncy);
            unsigned long long dz = fmx2(s->zs2[P], ONE2, ncz);
            unsigned long long dd = mulx2(dx, dx);
            dd = fmx2(dy, dy, dd);
            dd = fmx2(dz, dz, dd);
            float d0, d1; unpackf2(dd, d0, d1);
            float m0 = fminf(m[2 * j], d0);
            float m1 = fminf(m[2 * j + 1], d1);
            m[2 * j] = m0; m[2 * j + 1] = m1;
            bm = fmaxf(bm, fmaxf(m0, m1));
        }

        // ---- resolve smallest k with m[k]==bm (downward scan) ----
        int kk = 0;
#pragma unroll
        for (int k = NPT - 1; k >= 0; --k)
            if (m[k] == bm) kk = k;

        unsigned Pw   = (unsigned)(kk >> 1) * TPB + (unsigned)tid;
        unsigned gidx = pbase + 2u * Pw + (unsigned)(kk & 1);
        float a0, a1, b0, b1, c0, c1;
        unpackf2(s->xs2[Pw], a0, a1);
        unpackf2(s->ys2[Pw], b0, b1);
        unpackf2(s->zs2[Pw], c0, c1);
        float candx = (kk & 1) ? a1 : a0;
        float candy = (kk & 1) ? b1 : b0;
        float candz = (kk & 1) ? c1 : c0;

        // ---- warp reduce: max dist bits, then min index among maxima ----
        unsigned vb = __float_as_uint(bm);            // d>=0: int order == float order
        unsigned wv = __reduce_max_sync(0xffffffffu, vb);
        unsigned cd = (vb == wv) ? gidx : 0xffffffffu;
        unsigned wi = __reduce_min_sync(0xffffffffu, cd);
        if (cd == wi) {                               // unique winner lane stores
            *reinterpret_cast<uint4*>(&s->warpred[warp]) =
                make_uint4(wv, wi, __float_as_uint(candx), __float_as_uint(candy));
            s->warpred[warp].z = candz;
        }
        __syncthreads();

        const int par = t & 1;

        // ---- block reduce over 16 warp partials + push to all 8 peers ----
        if (warp == 0) {
            unsigned v = 0, i = 0xffffffffu, xb = 0, yb = 0, zb = 0;
            if (lane < NWARPS) {
                uint4 w = *reinterpret_cast<const uint4*>(&s->warpred[lane]);
                v = w.x; i = w.y; xb = w.z; yb = w.w;
                zb = __float_as_uint(s->warpred[lane].z);
            }
            unsigned bv = __reduce_max_sync(0xffffffffu, v);
            unsigned bc = (v == bv) ? i : 0xffffffffu;
            unsigned bi = __reduce_min_sync(0xffffffffu, bc);
            unsigned msk = __ballot_sync(0xffffffffu, bc == bi);
            int L = __ffs(msk) - 1;
            xb = __shfl_sync(0xffffffffu, xb, L);
            yb = __shfl_sync(0xffffffffu, yb, L);
            zb = __shfl_sync(0xffffffffu, zb, L);
            if (lane < CSIZE) {
                unsigned ra = par ? rs1 : rs0;
                st_cluster_v4(ra, bv, bi, xb, yb);
                st_cluster_u32(ra + 16, zb);
            }
        }

        // one cluster barrier per step (arrive releases the DSMEM stores)
        cluster_bar();

        // ---- EVERY warp reduces the 8 slots -> next centroid in registers ----
        {
            unsigned v = 0, i = 0xffffffffu, xb = 0, yb = 0, zb = 0;
            if (lane < CSIZE) {
                uint4 w = *reinterpret_cast<const uint4*>(&s->slots[par][lane]);
                v = w.x; i = w.y; xb = w.z; yb = w.w;
                zb = __float_as_uint(s->slots[par][lane].z);
            }
            unsigned cv = __reduce_max_sync(0xffffffffu, v);
            unsigned cc = (v == cv) ? i : 0xffffffffu;
            unsigned ci = __reduce_min_sync(0xffffffffu, cc);
            unsigned msk = __ballot_sync(0xffffffffu, cc == ci);
            int W = __ffs(msk) - 1;
            cx = __uint_as_float(__shfl_sync(0xffffffffu, xb, W));
            cy = __uint_as_float(__shfl_sync(0xffffffffu, yb, W));
            cz = __uint_as_float(__shfl_sync(0xffffffffu, zb, W));
            if (rank == 0 && tid == 0) {
                float* o = out + ((size_t)batch * NSAMP + (size_t)t) * 3;
                o[0] = cx; o[1] = cy; o[2] = cz;
            }
        }
        // warpred: each warp rewrites only its own entry after its own warp
        // stage; warp0 reads right after the block-wide __syncthreads.
        // slots: double-buffered by parity, protected by the cluster barrier.
    }

    cluster_bar();  // keep CTAs alive until all DSMEM traffic has landed
}

extern "C" void kernel_launch(void* const* d_in, const int* in_sizes, int n_in,
                              void* d_out, int out_size) {
    (void)in_sizes; (void)n_in; (void)out_size;
    const float* xyz = (const float*)d_in[0];
    float* out = (float*)d_out;

    cudaFuncSetAttribute(fps_kernel,
                         cudaFuncAttributeMaxDynamicSharedMemorySize,
                         (int)sizeof(Smem));

    cudaLaunchConfig_t cfg = {};
    cfg.gridDim  = dim3(NB * CSIZE, 1, 1);   // 64 CTAs
    cfg.blockDim = dim3(TPB, 1, 1);
    cfg.dynamicSmemBytes = sizeof(Smem);
    cfg.stream = 0;

    cudaLaunchAttribute attr[1];
    attr[0].id = cudaLaunchAttributeClusterDimension;
    attr[0].val.clusterDim.x = CSIZE;
    attr[0].val.clusterDim.y = 1;
    attr[0].val.clusterDim.z = 1;
    cfg.attrs = attr;
    cfg.numAttrs = 1;

    cudaLaunchKernelEx(&cfg, fps_kernel, xyz, out);
}

// round 16
// speedup vs baseline: 3.4047x; 1.0374x over previous
#include <cuda_runtime.h>
#include <cstdint>
#include <cstddef>

// FPS: B=8, N=131072, NPOINT=1024 -> out [8,1024,3] fp32.
// R14 champion (1527.6us) with ONE surgical change: streamed pairs store
// x/y interleaved (ulonglong2) so the per-pair shared traffic is one
// LDS.128 + one LDS.64 instead of three LDS.64 (-8 issue slots/thread/step).
// Candidate fetch branches on register-vs-streamed region (pattern proven in
// R8). Everything else byte-identical: 8 clusters x 8 CTAs x 512 thr;
// 16 pairs/thread (8 reg, 8 streamed); FFMA2 distance math; REDUX argmax
// (max dist, min index); coords ride the reduction -> DSMEM slots; ONE
// barrier.cluster per step; every warp reduces the 8 slots locally.

#define NB       8
#define NPTS     131072
#define NSAMP    1024
#define CSIZE    8
#define TPB      512
#define PPB      (NPTS / CSIZE)    // 16384 points per CTA
#define PAIRS    (PPB / 2)         // 8192 pairs per CTA
#define REGJ     8                 // pairs/thread in registers
#define TOTJ     16                // pairs/thread total
#define STRJ     (TOTJ - REGJ)     // 8 streamed pairs/thread
#define NPT      32                // points/thread
#define NWARPS   (TPB / 32)        // 16
#define APAIRS   (REGJ * TPB)      // 4096 pairs (register half, pair-major mirror)
#define BPAIRS   (STRJ * TPB)      // 4096 pairs (streamed half)

struct __align__(16) Red { unsigned v, i; float x, y, z; unsigned pad[3]; };  // 32B

struct Smem {
    Red warpred[NWARPS];
    Red slots[2][CSIZE];
    unsigned long long xa[APAIRS];   // register-half mirror (pair-major)
    unsigned long long ya[APAIRS];
    unsigned long long za[APAIRS];
    ulonglong2         xyb[BPAIRS];  // streamed half: {x2, y2} interleaved
    unsigned long long zb[BPAIRS];   // streamed half: z2
};

// ---------- asm helpers ----------
__device__ __forceinline__ unsigned ctarank() {
    unsigned r; asm("mov.u32 %0, %%cluster_ctarank;" : "=r"(r)); return r;
}
__device__ __forceinline__ unsigned cvta_s(const void* p) {
    unsigned r;
    asm("{ .reg .u64 t; cvta.to.shared.u64 t, %1; cvt.u32.u64 %0, t; }"
        : "=r"(r) : "l"(p));
    return r;
}
__device__ __forceinline__ unsigned mapa_s(unsigned laddr, unsigned rank) {
    unsigned r;
    asm("mapa.shared::cluster.u32 %0, %1, %2;" : "=r"(r) : "r"(laddr), "r"(rank));
    return r;
}
__device__ __forceinline__ unsigned long long packf2(float lo, float hi) {
    unsigned long long r;
    asm("mov.b64 %0, {%1, %2};" : "=l"(r) : "f"(lo), "f"(hi));
    return r;
}
__device__ __forceinline__ void unpackf2(unsigned long long v, float& lo, float& hi) {
    asm("mov.b64 {%0, %1}, %2;" : "=f"(lo), "=f"(hi) : "l"(v));
}
__device__ __forceinline__ unsigned long long mulx2(unsigned long long a,
                                                    unsigned long long b) {
    unsigned long long r;
    asm("mul.rn.f32x2 %0, %1, %2;" : "=l"(r) : "l"(a), "l"(b));
    return r;
}
__device__ __forceinline__ unsigned long long fmx2(unsigned long long a,
                                                   unsigned long long b,
                                                   unsigned long long c) {
    unsigned long long r;
    asm("fma.rn.f32x2 %0, %1, %2, %3;" : "=l"(r) : "l"(a), "l"(b), "l"(c));
    return r;
}
__device__ __forceinline__ void st_cluster_v4(unsigned raddr, unsigned a, unsigned b,
                                              unsigned c, unsigned d) {
    asm volatile("st.shared::cluster.v4.b32 [%0], {%1,%2,%3,%4};"
                 :: "r"(raddr), "r"(a), "r"(b), "r"(c), "r"(d) : "memory");
}
__device__ __forceinline__ void st_cluster_u32(unsigned raddr, unsigned v) {
    asm volatile("st.shared::cluster.u32 [%0], %1;" :: "r"(raddr), "r"(v) : "memory");
}
__device__ __forceinline__ void cluster_bar() {
    asm volatile("barrier.cluster.arrive.aligned;" ::: "memory");
    asm volatile("barrier.cluster.wait.aligned;"   ::: "memory");
}

__global__ void __launch_bounds__(TPB, 1)
fps_kernel(const float* __restrict__ xyz, float* __restrict__ out) {
    extern __shared__ __align__(16) unsigned char smem_raw[];
    Smem* s = reinterpret_cast<Smem*>(smem_raw);

    const int      tid  = threadIdx.x;
    const unsigned lane = tid & 31;
    const unsigned warp = (unsigned)tid >> 5;
    const unsigned rank = ctarank();
    const int      batch = blockIdx.x / CSIZE;

    const float* __restrict__ base = xyz + (size_t)batch * NPTS * 3;
    const unsigned pbase = rank * PPB;

    // ---- load: reg pairs -> registers + pair-major mirror;
    //            streamed pairs -> interleaved xy + z ----
    unsigned long long X[REGJ], Y[REGJ], Z[REGJ];
#pragma unroll
    for (int j = 0; j < TOTJ; ++j) {
        unsigned P = (unsigned)j * TPB + (unsigned)tid;   // global pair id in CTA
        const float2* p = reinterpret_cast<const float2*>(
            base + (size_t)(pbase + 2u * P) * 3);
        float2 a = p[0];  // x0 y0
        float2 b = p[1];  // z0 x1
        float2 c = p[2];  // y1 z1
        unsigned long long px = packf2(a.x, b.y);
        unsigned long long py = packf2(a.y, c.x);
        unsigned long long pz = packf2(b.x, c.y);
        if (j < REGJ) {
            X[j] = px; Y[j] = py; Z[j] = pz;
            s->xa[P] = px; s->ya[P] = py; s->za[P] = pz;
        } else {
            unsigned q = (unsigned)(j - REGJ) * TPB + (unsigned)tid;
            s->xyb[q] = make_ulonglong2(px, py);
            s->zb[q]  = pz;
        }
    }

    float m[NPT];
#pragma unroll
    for (int k = 0; k < NPT; ++k) m[k] = __int_as_float(0x7f800000);  // +inf

    // remote slot addresses for pushes (warp0 lanes < CSIZE), both parities
    unsigned rs0 = 0, rs1 = 0;
    if (warp == 0 && lane < CSIZE) {
        rs0 = mapa_s(cvta_s(&s->slots[0][rank]), lane);
        rs1 = mapa_s(cvta_s(&s->slots[1][rank]), lane);
    }

    // initial centroid = point 0 of this batch (broadcast L2 load, once)
    float cx = __ldg(base + 0);
    float cy = __ldg(base + 1);
    float cz = __ldg(base + 2);
    if (rank == 0 && tid == 0) {
        float* o = out + (size_t)batch * NSAMP * 3;
        o[0] = cx; o[1] = cy; o[2] = cz;
    }
    __syncthreads();   // smem ready

    const unsigned long long ONE2 = packf2(1.0f, 1.0f);

    for (int t = 1; t < NSAMP; ++t) {
        const unsigned long long ncx = packf2(-cx, -cx);
        const unsigned long long ncy = packf2(-cy, -cy);
        const unsigned long long ncz = packf2(-cz, -cz);

        float bm = -1.0f;

        // ---- register pairs (no LDS) ----
#pragma unroll
        for (int j = 0; j < REGJ; ++j) {
            unsigned long long dx = fmx2(X[j], ONE2, ncx);
            unsigned long long dy = fmx2(Y[j], ONE2, ncy);
            unsigned long long dz = fmx2(Z[j], ONE2, ncz);
            unsigned long long dd = mulx2(dx, dx);
            dd = fmx2(dy, dy, dd);
            dd = fmx2(dz, dz, dd);
            float d0, d1; unpackf2(dd, d0, d1);
            float m0 = fminf(m[2 * j], d0);
            float m1 = fminf(m[2 * j + 1], d1);
            m[2 * j] = m0; m[2 * j + 1] = m1;
            bm = fmaxf(bm, fmaxf(m0, m1));
        }
        // ---- streamed pairs: LDS.128 (xy) + LDS.64 (z) per pair ----
#pragma unroll
        for (int j = REGJ; j < TOTJ; ++j) {
            unsigned q = (unsigned)(j - REGJ) * TPB + (unsigned)tid;
            ulonglong2 xy = s->xyb[q];
            unsigned long long zp = s->zb[q];
            unsigned long long dx = fmx2(xy.x, ONE2, ncx);
            unsigned long long dy = fmx2(xy.y, ONE2, ncy);
            unsigned long long dz = fmx2(zp,   ONE2, ncz);
            unsigned long long dd = mulx2(dx, dx);
            dd = fmx2(dy, dy, dd);
            dd = fmx2(dz, dz, dd);
            float d0, d1; unpackf2(dd, d0, d1);
            float m0 = fminf(m[2 * j], d0);
            float m1 = fminf(m[2 * j + 1], d1);
            m[2 * j] = m0; m[2 * j + 1] = m1;
            bm = fmaxf(bm, fmaxf(m0, m1));
        }

        // ---- resolve smallest k with m[k]==bm (downward scan) ----
        int kk = 0;
#pragma unroll
        for (int k = NPT - 1; k >= 0; --k)
            if (m[k] == bm) kk = k;

        const unsigned jw   = (unsigned)kk >> 1;
        const unsigned Pw   = jw * TPB + (unsigned)tid;
        const unsigned gidx = pbase + 2u * Pw + (unsigned)(kk & 1);

        unsigned long long wx, wy, wz;
        if (jw < REGJ) {
            wx = s->xa[Pw]; wy = s->ya[Pw]; wz = s->za[Pw];
        } else {
            unsigned q = (jw - REGJ) * TPB + (unsigned)tid;
            ulonglong2 xy = s->xyb[q];
            wx = xy.x; wy = xy.y; wz = s->zb[q];
        }
        float a0, a1, b0, b1, c0, c1;
        unpackf2(wx, a0, a1);
        unpackf2(wy, b0, b1);
        unpackf2(wz, c0, c1);
        float candx = (kk & 1) ? a1 : a0;
        float candy = (kk & 1) ? b1 : b0;
        float candz = (kk & 1) ? c1 : c0;

        // ---- warp reduce: max dist bits, then min index among maxima ----
        unsigned vb = __float_as_uint(bm);            // d>=0: int order == float order
        unsigned wv = __reduce_max_sync(0xffffffffu, vb);
        unsigned cd = (vb == wv) ? gidx : 0xffffffffu;
        unsigned wi = __reduce_min_sync(0xffffffffu, cd);
        if (cd == wi) {                               // unique winner lane stores
            *reinterpret_cast<uint4*>(&s->warpred[warp]) =
                make_uint4(wv, wi, __float_as_uint(candx), __float_as_uint(candy));
            s->warpred[warp].z = candz;
        }
        __syncthreads();

        const int par = t & 1;

        // ---- block reduce over 16 warp partials + push to all 8 peers ----
        if (warp == 0) {
            unsigned v = 0, i = 0xffffffffu, xb = 0, yb = 0, zb = 0;
            if (lane < NWARPS) {
                uint4 w = *reinterpret_cast<const uint4*>(&s->warpred[lane]);
                v = w.x; i = w.y; xb = w.z; yb = w.w;
                zb = __float_as_uint(s->warpred[lane].z);
            }
            unsigned bv = __reduce_max_sync(0xffffffffu, v);
            unsigned bc = (v == bv) ? i : 0xffffffffu;
            unsigned bi = __reduce_min_sync(0xffffffffu, bc);
            unsigned msk = __ballot_sync(0xffffffffu, bc == bi);
            int L = __ffs(msk) - 1;
            xb = __shfl_sync(0xffffffffu, xb, L);
            yb = __shfl_sync(0xffffffffu, yb, L);
            zb = __shfl_sync(0xffffffffu, zb, L);
            if (lane < CSIZE) {
                unsigned ra = par ? rs1 : rs0;
                st_cluster_v4(ra, bv, bi, xb, yb);
                st_cluster_u32(ra + 16, zb);
            }
        }

        // one cluster barrier per step (arrive releases the DSMEM stores)
        cluster_bar();

        // ---- EVERY warp reduces the 8 slots -> next centroid in registers ----
        {
            unsigned v = 0, i = 0xffffffffu, xb = 0, yb = 0, zb = 0;
            if (lane < CSIZE) {
                uint4 w = *reinterpret_cast<const uint4*>(&s->slots[par][lane]);
                v = w.x; i = w.y; xb = w.z; yb = w.w;
                zb = __float_as_uint(s->slots[par][lane].z);
            }
            unsigned cv = __reduce_max_sync(0xffffffffu, v);
            unsigned cc = (v == cv) ? i : 0xffffffffu;
            unsigned ci = __reduce_min_sync(0xffffffffu, cc);
            unsigned msk = __ballot_sync(0xffffffffu, cc == ci);
            int W = __ffs(msk) - 1;
            cx = __uint_as_float(__shfl_sync(0xffffffffu, xb, W));
            cy = __uint_as_float(__shfl_sync(0xffffffffu, yb, W));
            cz = __uint_as_float(__shfl_sync(0xffffffffu, zb, W));
            if (rank == 0 && tid == 0) {
                float* o = out + ((size_t)batch * NSAMP + (size_t)t) * 3;
                o[0] = cx; o[1] = cy; o[2] = cz;
            }
        }
        // warpred: each warp rewrites only its own entry after its own warp
        // stage; warp0 reads right after the block-wide __syncthreads.
        // slots: double-buffered by parity, protected by the cluster barrier.
    }

    cluster_bar();  // keep CTAs alive until all DSMEM traffic has landed
}

extern "C" void kernel_launch(void* const* d_in, const int* in_sizes, int n_in,
                              void* d_out, int out_size) {
    (void)in_sizes; (void)n_in; (void)out_size;
    const float* xyz = (const float*)d_in[0];
    float* out = (float*)d_out;

    cudaFuncSetAttribute(fps_kernel,
                         cudaFuncAttributeMaxDynamicSharedMemorySize,
                         (int)sizeof(Smem));

    cudaLaunchConfig_t cfg = {};
    cfg.gridDim  = dim3(NB * CSIZE, 1, 1);   // 64 CTAs
    cfg.blockDim = dim3(TPB, 1, 1);
    cfg.dynamicSmemBytes = sizeof(Smem);
    cfg.stream = 0;

    cudaLaunchAttribute attr[1];
    attr[0].id = cudaLaunchAttributeClusterDimension;
    attr[0].val.clusterDim.x = CSIZE;
    attr[0].val.clusterDim.y = 1;
    attr[0].val.clusterDim.z = 1;
    cfg.attrs = attr;
    cfg.numAttrs = 1;

    cudaLaunchKernelEx(&cfg, fps_kernel, xyz, out);
}